// round 1
// baseline (speedup 1.0000x reference)
#include <cuda_runtime.h>

// Problem constants (fixed by reference): B=4, H=8, S=2048, D=3
#define S_LEN   2048
#define N_BH    32            // B*H
#define QPC     64            // queries per CTA
#define KG      4             // key groups per CTA (split-K inside CTA)
#define KPG     (S_LEN / KG)  // 512 keys per group
#define THREADS 256
#define N_CTA   (N_BH * (S_LEN / QPC))   // 32 * 32 = 1024
#define OUT_HALF (N_BH * S_LEN * 3)      // 196608 ; output is (ctx, ctx)

// smem layout (floats):
//   kv4 : 2048 * float4  (k0,k1,k2,v0)   -> 8192 floats
//   kv2 : 2048 * float2  (v1,v2)         -> 4096 floats
//   red : 5 * 256 floats (m,l,a0,a1,a2)  -> 1280 floats
#define SMEM_FLOATS (8192 + 4096 + 1280)
#define SMEM_BYTES  (SMEM_FLOATS * 4)    // 54272

__device__ __forceinline__ float ex2(float x) {
    float r;
    asm("ex2.approx.f32 %0, %1;" : "=f"(r) : "f"(x));
    return r;
}

__global__ __launch_bounds__(THREADS, 4)
void attn3d_kernel(const float* __restrict__ x,
                   const float* __restrict__ Wq,
                   const float* __restrict__ Wk,
                   const float* __restrict__ Wv,
                   float* __restrict__ out)
{
    extern __shared__ float sm[];
    float4* kv4 = reinterpret_cast<float4*>(sm);
    float2* kv2 = reinterpret_cast<float2*>(sm + 8192);
    float*  red = sm + 8192 + 4096;

    const int tid   = threadIdx.x;
    const int cta   = blockIdx.x;
    const int bh    = cta >> 5;        // /(S/QPC)=32 chunks per bh
    const int chunk = cta & 31;
    const int b     = bh >> 3;
    const int h     = bh & 7;

    // Per-head weights (uniform across block; 3x3 row-major W[d][e])
    const float* wq = Wq + h * 9;
    const float* wk = Wk + h * 9;
    const float* wv = Wv + h * 9;
    const float k00 = wk[0], k01 = wk[1], k02 = wk[2];
    const float k10 = wk[3], k11 = wk[4], k12 = wk[5];
    const float k20 = wk[6], k21 = wk[7], k22 = wk[8];
    const float v00 = wv[0], v01 = wv[1], v02 = wv[2];
    const float v10 = wv[3], v11 = wv[4], v12 = wv[5];
    const float v20 = wv[6], v21 = wv[7], v22 = wv[8];

    const float* xb = x + (size_t)b * S_LEN * 3;

    // ---- Fill K,V for this (b,h) into smem (projected on the fly) ----
    #pragma unroll
    for (int i = tid; i < S_LEN; i += THREADS) {
        const float x0 = xb[i * 3 + 0];
        const float x1 = xb[i * 3 + 1];
        const float x2 = xb[i * 3 + 2];
        const float kk0 = x0 * k00 + x1 * k10 + x2 * k20;
        const float kk1 = x0 * k01 + x1 * k11 + x2 * k21;
        const float kk2 = x0 * k02 + x1 * k12 + x2 * k22;
        const float vv0 = x0 * v00 + x1 * v10 + x2 * v20;
        const float vv1 = x0 * v01 + x1 * v11 + x2 * v21;
        const float vv2 = x0 * v02 + x1 * v12 + x2 * v22;
        kv4[i] = make_float4(kk0, kk1, kk2, vv0);
        kv2[i] = make_float2(vv1, vv2);
    }

    // ---- This thread's query (pre-scaled into exp2 domain) ----
    const int g  = tid >> 6;      // key group 0..3 (each warp wholly in one group)
    const int ql = tid & 63;      // query within chunk
    const int sq = chunk * QPC + ql;
    {
        // nothing
    }
    const float xq0 = xb[sq * 3 + 0];
    const float xq1 = xb[sq * 3 + 1];
    const float xq2 = xb[sq * 3 + 2];
    // scale = 1/sqrt(3); fold log2(e) so scores are in exp2 units
    const float RS = 0.57735026918962576f * 1.4426950408889634f;
    const float q0 = (xq0 * wq[0] + xq1 * wq[3] + xq2 * wq[6]) * RS;
    const float q1 = (xq0 * wq[1] + xq1 * wq[4] + xq2 * wq[7]) * RS;
    const float q2 = (xq0 * wq[2] + xq1 * wq[5] + xq2 * wq[8]) * RS;

    __syncthreads();

    // ---- Online softmax over this thread's key group ----
    float m = -1e30f, l = 0.0f, a0 = 0.0f, a1 = 0.0f, a2 = 0.0f;
    const int kbeg = g * KPG;
    #pragma unroll 4
    for (int k = kbeg; k < kbeg + KPG; ++k) {
        const float4 c4 = kv4[k];   // broadcast LDS.128
        const float2 c2 = kv2[k];   // broadcast LDS.64
        const float d = q0 * c4.x + q1 * c4.y + q2 * c4.z;
        if (__builtin_expect(d > m, 0)) {       // rare: new running max
            const float c = ex2(m - d);
            l *= c; a0 *= c; a1 *= c; a2 *= c;
            m = d;
        }
        const float p = ex2(d - m);
        l  += p;
        a0 += p * c4.w;
        a1 += p * c2.x;
        a2 += p * c2.y;
    }

    // ---- 4-way merge across key groups ----
    red[tid]            = m;
    red[256  + tid]     = l;
    red[512  + tid]     = a0;
    red[768  + tid]     = a1;
    red[1024 + tid]     = a2;
    __syncthreads();

    if (tid < QPC) {
        float M = red[tid];
        #pragma unroll
        for (int gg = 1; gg < KG; ++gg)
            M = fmaxf(M, red[gg * 64 + tid]);
        float L = 0.0f, A0 = 0.0f, A1 = 0.0f, A2 = 0.0f;
        #pragma unroll
        for (int gg = 0; gg < KG; ++gg) {
            const int o = gg * 64 + tid;
            const float sc = ex2(red[o] - M);
            L  += red[256  + o] * sc;
            A0 += red[512  + o] * sc;
            A1 += red[768  + o] * sc;
            A2 += red[1024 + o] * sc;
        }
        const float inv = __frcp_rn(L);
        const int s_out = chunk * QPC + tid;
        const int base  = (bh * S_LEN + s_out) * 3;
        const float r0 = A0 * inv, r1 = A1 * inv, r2 = A2 * inv;
        out[base + 0] = r0;
        out[base + 1] = r1;
        out[base + 2] = r2;
        out[OUT_HALF + base + 0] = r0;
        out[OUT_HALF + base + 1] = r1;
        out[OUT_HALF + base + 2] = r2;
    }
}

extern "C" void kernel_launch(void* const* d_in, const int* in_sizes, int n_in,
                              void* d_out, int out_size)
{
    const float* x  = (const float*)d_in[0];
    const float* Wq = (const float*)d_in[1];
    const float* Wk = (const float*)d_in[2];
    const float* Wv = (const float*)d_in[3];
    float* out = (float*)d_out;

    cudaFuncSetAttribute(attn3d_kernel,
                         cudaFuncAttributeMaxDynamicSharedMemorySize, SMEM_BYTES);
    attn3d_kernel<<<N_CTA, THREADS, SMEM_BYTES>>>(x, Wq, Wk, Wv, out);
}

// round 3
// speedup vs baseline: 1.4882x; 1.4882x over previous
#include <cuda_runtime.h>

// B=4, H=8, S=2048, D=3 (fixed by reference)
typedef unsigned long long u64;

#define S_LEN   2048
#define QPC     64           // queries per CTA
#define THREADS 128          // 2 key-groups x 64 queries
#define N_CTA   1024         // 32 bh * 32 chunks
#define OUT_HALF (32 * S_LEN * 3)

// smem (floats): 512 quad records * 12 floats (x0[4],x1[4],x2[4]) = 6144
//                red: 4 * 128                                     = 512
//                wmax: 4 warps * 3 (+pad)                         = 16
#define SM_RED    6144
#define SM_WMAX   (6144 + 512)
#define SMEM_BYTES ((6144 + 512 + 16) * 4)

__device__ __forceinline__ u64 fma2(u64 a, u64 b, u64 c) {
    u64 d; asm("fma.rn.f32x2 %0, %1, %2, %3;" : "=l"(d) : "l"(a), "l"(b), "l"(c));
    return d;
}
__device__ __forceinline__ u64 add2(u64 a, u64 b) {
    u64 d; asm("add.rn.f32x2 %0, %1, %2;" : "=l"(d) : "l"(a), "l"(b));
    return d;
}
__device__ __forceinline__ u64 ex2_2(u64 x) {
    u64 r;
    asm("{\n\t"
        ".reg .f32 lo, hi;\n\t"
        "mov.b64 {lo, hi}, %1;\n\t"
        "ex2.approx.f32 lo, lo;\n\t"
        "ex2.approx.f32 hi, hi;\n\t"
        "mov.b64 %0, {lo, hi};\n\t"
        "}" : "=l"(r) : "l"(x));
    return r;
}
__device__ __forceinline__ u64 pack2(float lo, float hi) {
    u64 r; asm("mov.b64 %0, {%1, %2};" : "=l"(r) : "f"(lo), "f"(hi));
    return r;
}
__device__ __forceinline__ void unpack2(u64 v, float& lo, float& hi) {
    asm("mov.b64 {%0, %1}, %2;" : "=f"(lo), "=f"(hi) : "l"(v));
}
__device__ __forceinline__ float rcpa(float x) {
    float r; asm("rcp.approx.f32 %0, %1;" : "=f"(r) : "f"(x));
    return r;
}

__global__ __launch_bounds__(THREADS, 8)
void attn3d_kernel(const float* __restrict__ x,
                   const float* __restrict__ Wq,
                   const float* __restrict__ Wk,
                   const float* __restrict__ Wv,
                   float* __restrict__ out)
{
    extern __shared__ float sm[];
    float* red  = sm + SM_RED;
    float* wmax = sm + SM_WMAX;

    const int tid   = threadIdx.x;
    const int cta   = blockIdx.x;
    const int bh    = cta >> 5;        // 32 chunks per (b,h)
    const int chunk = cta & 31;
    const int b     = bh >> 3;
    const int h     = bh & 7;

    const float* xb = x + (size_t)b * S_LEN * 3;

    // ---- Fill smem with raw x (quad-packed SoA) + track per-component max|x| ----
    float M0 = 0.f, M1 = 0.f, M2 = 0.f;
    #pragma unroll
    for (int i = 0; i < S_LEN / THREADS; ++i) {
        const int k = tid + i * THREADS;
        const float x0 = xb[k * 3 + 0];
        const float x1 = xb[k * 3 + 1];
        const float x2 = xb[k * 3 + 2];
        const int j = k >> 2, c = k & 3;           // quad, lane-in-quad
        sm[j * 12 + 0 + c] = x0;
        sm[j * 12 + 4 + c] = x1;
        sm[j * 12 + 8 + c] = x2;
        M0 = fmaxf(M0, fabsf(x0));
        M1 = fmaxf(M1, fabsf(x1));
        M2 = fmaxf(M2, fabsf(x2));
    }
    // warp-level max (nonneg floats: uint order == float order)
    unsigned u0 = __reduce_max_sync(0xffffffffu, __float_as_uint(M0));
    unsigned u1 = __reduce_max_sync(0xffffffffu, __float_as_uint(M1));
    unsigned u2 = __reduce_max_sync(0xffffffffu, __float_as_uint(M2));
    if ((tid & 31) == 0) {
        const int w = tid >> 5;
        wmax[w * 3 + 0] = __uint_as_float(u0);
        wmax[w * 3 + 1] = __uint_as_float(u1);
        wmax[w * 3 + 2] = __uint_as_float(u2);
    }

    // ---- Query: q = x_q @ Wq ; fold Wk + scale:  qt_d = RS * sum_e q_e Wk[d][e] ----
    const int g  = tid >> 6;           // key group 0/1
    const int ql = tid & 63;
    const int sq = chunk * QPC + ql;
    const float xq0 = xb[sq * 3 + 0];
    const float xq1 = xb[sq * 3 + 1];
    const float xq2 = xb[sq * 3 + 2];
    const float* wq = Wq + h * 9;
    const float* wk = Wk + h * 9;
    const float q0 = xq0 * wq[0] + xq1 * wq[3] + xq2 * wq[6];
    const float q1 = xq0 * wq[1] + xq1 * wq[4] + xq2 * wq[7];
    const float q2 = xq0 * wq[2] + xq1 * wq[5] + xq2 * wq[8];
    // scale = 1/sqrt(3) * log2(e)  (exp2 domain)
    const float RS = 0.57735026918962576f * 1.4426950408889634f;
    const float qt0 = RS * (q0 * wk[0] + q1 * wk[1] + q2 * wk[2]);
    const float qt1 = RS * (q0 * wk[3] + q1 * wk[4] + q2 * wk[5]);
    const float qt2 = RS * (q0 * wk[6] + q1 * wk[7] + q2 * wk[8]);

    __syncthreads();

    // ---- Fixed softmax shift: guaranteed upper bound on any score ----
    const float MM0 = fmaxf(fmaxf(wmax[0], wmax[3]), fmaxf(wmax[6], wmax[9]));
    const float MM1 = fmaxf(fmaxf(wmax[1], wmax[4]), fmaxf(wmax[7], wmax[10]));
    const float MM2 = fmaxf(fmaxf(wmax[2], wmax[5]), fmaxf(wmax[8], wmax[11]));
    const float m = fabsf(qt0) * MM0 + fabsf(qt1) * MM1 + fabsf(qt2) * MM2 + 1.0f;

    const u64 q0p = pack2(qt0, qt0);
    const u64 q1p = pack2(qt1, qt1);
    const u64 q2p = pack2(qt2, qt2);
    const u64 nm  = pack2(-m, -m);

    // ---- Inner loop: 256 quads (1024 keys) of packed-pair math ----
    u64 lA = 0ull, lB = 0ull;
    u64 t0A = 0ull, t0B = 0ull, t1A = 0ull, t1B = 0ull, t2A = 0ull, t2B = 0ull;
    const ulonglong2* P = reinterpret_cast<const ulonglong2*>(sm) + g * 768;
    #pragma unroll 2
    for (int j = 0; j < 256; ++j) {
        const ulonglong2 X0 = P[0];   // x0 of keys 4j..4j+3, as two f32x2 pairs
        const ulonglong2 X1 = P[1];
        const ulonglong2 X2 = P[2];
        P += 3;
        const u64 dA = fma2(q0p, X0.x, fma2(q1p, X1.x, fma2(q2p, X2.x, nm)));
        const u64 dB = fma2(q0p, X0.y, fma2(q1p, X1.y, fma2(q2p, X2.y, nm)));
        const u64 pA = ex2_2(dA);
        const u64 pB = ex2_2(dB);
        lA  = add2(lA, pA);        lB  = add2(lB, pB);
        t0A = fma2(pA, X0.x, t0A); t0B = fma2(pB, X0.y, t0B);
        t1A = fma2(pA, X1.x, t1A); t1B = fma2(pB, X1.y, t1B);
        t2A = fma2(pA, X2.x, t2A); t2B = fma2(pB, X2.y, t2B);
    }

    // ---- Collapse packed lanes; 2-way group merge (same m => plain sums) ----
    float a, c2;
    float l, t0, t1, t2;
    unpack2(lA, a, c2);  l  = a + c2;  unpack2(lB, a, c2);  l  += a + c2;
    unpack2(t0A, a, c2); t0 = a + c2;  unpack2(t0B, a, c2); t0 += a + c2;
    unpack2(t1A, a, c2); t1 = a + c2;  unpack2(t1B, a, c2); t1 += a + c2;
    unpack2(t2A, a, c2); t2 = a + c2;  unpack2(t2B, a, c2); t2 += a + c2;

    red[tid]       = l;
    red[128 + tid] = t0;
    red[256 + tid] = t1;
    red[384 + tid] = t2;
    __syncthreads();

    if (tid < QPC) {
        const float L  = red[tid]       + red[64 + tid];
        const float T0 = red[128 + tid] + red[192 + tid];
        const float T1 = red[256 + tid] + red[320 + tid];
        const float T2 = red[384 + tid] + red[448 + tid];
        const float inv = rcpa(L);
        const float* wv = Wv + h * 9;
        const float r0 = (T0 * wv[0] + T1 * wv[3] + T2 * wv[6]) * inv;
        const float r1 = (T0 * wv[1] + T1 * wv[4] + T2 * wv[7]) * inv;
        const float r2 = (T0 * wv[2] + T1 * wv[5] + T2 * wv[8]) * inv;
        const int s_out = chunk * QPC + tid;
        const int base  = (bh * S_LEN + s_out) * 3;
        out[base + 0] = r0;
        out[base + 1] = r1;
        out[base + 2] = r2;
        out[OUT_HALF + base + 0] = r0;
        out[OUT_HALF + base + 1] = r1;
        out[OUT_HALF + base + 2] = r2;
    }
}

extern "C" void kernel_launch(void* const* d_in, const int* in_sizes, int n_in,
                              void* d_out, int out_size)
{
    const float* x  = (const float*)d_in[0];
    const float* Wq = (const float*)d_in[1];
    const float* Wk = (const float*)d_in[2];
    const float* Wv = (const float*)d_in[3];
    float* out = (float*)d_out;

    cudaFuncSetAttribute(attn3d_kernel,
                         cudaFuncAttributeMaxDynamicSharedMemorySize, SMEM_BYTES);
    attn3d_kernel<<<N_CTA, THREADS, SMEM_BYTES>>>(x, Wq, Wk, Wv, out);
}

// round 4
// speedup vs baseline: 1.6466x; 1.1065x over previous
#include <cuda_runtime.h>

// B=4, H=8, S=2048, D=3 (fixed by reference)
typedef unsigned long long u64;

#define S_LEN   2048
#define QPC     64            // queries per CTA
#define THREADS 128           // 4 key-groups x 32 threads; 2 queries per thread
#define N_CTA   1024          // 32 bh * 32 chunks
#define KPG     512           // keys per group (KG=4)
#define OUT_HALF (32 * S_LEN * 3)

// smem (floats): x quads: 512 * 12 = 6144 ; red: 4 vals * 4 groups * 64 q = 1024 ; wmax 16
#define SM_RED    6144
#define SM_WMAX   (6144 + 1024)
#define SMEM_BYTES ((6144 + 1024 + 16) * 4)   // 28736 B -> 7 CTAs/SM

__device__ __forceinline__ u64 fma2(u64 a, u64 b, u64 c) {
    u64 d; asm("fma.rn.f32x2 %0, %1, %2, %3;" : "=l"(d) : "l"(a), "l"(b), "l"(c));
    return d;
}
__device__ __forceinline__ u64 add2(u64 a, u64 b) {
    u64 d; asm("add.rn.f32x2 %0, %1, %2;" : "=l"(d) : "l"(a), "l"(b));
    return d;
}
__device__ __forceinline__ u64 ex2_2(u64 x) {
    u64 r;
    asm("{\n\t"
        ".reg .f32 lo, hi;\n\t"
        "mov.b64 {lo, hi}, %1;\n\t"
        "ex2.approx.f32 lo, lo;\n\t"
        "ex2.approx.f32 hi, hi;\n\t"
        "mov.b64 %0, {lo, hi};\n\t"
        "}" : "=l"(r) : "l"(x));
    return r;
}
__device__ __forceinline__ u64 pack2(float lo, float hi) {
    u64 r; asm("mov.b64 %0, {%1, %2};" : "=l"(r) : "f"(lo), "f"(hi));
    return r;
}
__device__ __forceinline__ void unpack2(u64 v, float& lo, float& hi) {
    asm("mov.b64 {%0, %1}, %2;" : "=f"(lo), "=f"(hi) : "l"(v));
}
__device__ __forceinline__ float rcpa(float x) {
    float r; asm("rcp.approx.f32 %0, %1;" : "=f"(r) : "f"(x));
    return r;
}

__global__ __launch_bounds__(THREADS, 7)
void attn3d_kernel(const float* __restrict__ x,
                   const float* __restrict__ Wq,
                   const float* __restrict__ Wk,
                   const float* __restrict__ Wv,
                   float* __restrict__ out)
{
    extern __shared__ float sm[];
    float* red  = sm + SM_RED;
    float* wmax = sm + SM_WMAX;

    const int tid   = threadIdx.x;
    const int cta   = blockIdx.x;
    const int bh    = cta >> 5;
    const int chunk = cta & 31;
    const int b     = bh >> 3;
    const int h     = bh & 7;

    const float* xb = x + (size_t)b * S_LEN * 3;

    // ---- Fill smem with raw x (quad-packed SoA) + per-component max|x| ----
    float M0 = 0.f, M1 = 0.f, M2 = 0.f;
    #pragma unroll
    for (int i = 0; i < S_LEN / THREADS; ++i) {
        const int k = tid + i * THREADS;
        const float x0 = xb[k * 3 + 0];
        const float x1 = xb[k * 3 + 1];
        const float x2 = xb[k * 3 + 2];
        const int j = k >> 2, c = k & 3;
        sm[j * 12 + 0 + c] = x0;
        sm[j * 12 + 4 + c] = x1;
        sm[j * 12 + 8 + c] = x2;
        M0 = fmaxf(M0, fabsf(x0));
        M1 = fmaxf(M1, fabsf(x1));
        M2 = fmaxf(M2, fabsf(x2));
    }
    unsigned u0 = __reduce_max_sync(0xffffffffu, __float_as_uint(M0));
    unsigned u1 = __reduce_max_sync(0xffffffffu, __float_as_uint(M1));
    unsigned u2 = __reduce_max_sync(0xffffffffu, __float_as_uint(M2));
    if ((tid & 31) == 0) {
        const int w = tid >> 5;
        wmax[w * 3 + 0] = __uint_as_float(u0);
        wmax[w * 3 + 1] = __uint_as_float(u1);
        wmax[w * 3 + 2] = __uint_as_float(u2);
    }

    // ---- Two queries per thread ----
    const int g  = tid >> 5;           // key group 0..3
    const int ql = tid & 31;           // query slot: handles ql and ql+32
    const float* wq = Wq + h * 9;
    const float* wk = Wk + h * 9;
    const float RS = 0.57735026918962576f * 1.4426950408889634f;

    float qt0[2], qt1[2], qt2[2];
    #pragma unroll
    for (int qq = 0; qq < 2; ++qq) {
        const int sq = chunk * QPC + ql + qq * 32;
        const float xq0 = xb[sq * 3 + 0];
        const float xq1 = xb[sq * 3 + 1];
        const float xq2 = xb[sq * 3 + 2];
        const float q0 = xq0 * wq[0] + xq1 * wq[3] + xq2 * wq[6];
        const float q1 = xq0 * wq[1] + xq1 * wq[4] + xq2 * wq[7];
        const float q2 = xq0 * wq[2] + xq1 * wq[5] + xq2 * wq[8];
        qt0[qq] = RS * (q0 * wk[0] + q1 * wk[1] + q2 * wk[2]);
        qt1[qq] = RS * (q0 * wk[3] + q1 * wk[4] + q2 * wk[5]);
        qt2[qq] = RS * (q0 * wk[6] + q1 * wk[7] + q2 * wk[8]);
    }

    __syncthreads();

    // ---- Fixed softmax shift per query ----
    const float MM0 = fmaxf(fmaxf(wmax[0], wmax[3]), fmaxf(wmax[6], wmax[9]));
    const float MM1 = fmaxf(fmaxf(wmax[1], wmax[4]), fmaxf(wmax[7], wmax[10]));
    const float MM2 = fmaxf(fmaxf(wmax[2], wmax[5]), fmaxf(wmax[8], wmax[11]));

    u64 q0p[2], q1p[2], q2p[2], nm[2];
    #pragma unroll
    for (int qq = 0; qq < 2; ++qq) {
        const float m = fabsf(qt0[qq]) * MM0 + fabsf(qt1[qq]) * MM1
                      + fabsf(qt2[qq]) * MM2 + 1.0f;
        q0p[qq] = pack2(qt0[qq], qt0[qq]);
        q1p[qq] = pack2(qt1[qq], qt1[qq]);
        q2p[qq] = pack2(qt2[qq], qt2[qq]);
        nm[qq]  = pack2(-m, -m);
    }

    // ---- Inner loop: 128 quads (512 keys) x 2 queries ----
    u64 lacc[2] = {0ull, 0ull};
    u64 t0[2] = {0ull, 0ull}, t1[2] = {0ull, 0ull}, t2[2] = {0ull, 0ull};
    const ulonglong2* P = reinterpret_cast<const ulonglong2*>(sm) + g * 384;
    #pragma unroll 2
    for (int j = 0; j < KPG / 4; ++j) {
        const ulonglong2 X0 = P[0];
        const ulonglong2 X1 = P[1];
        const ulonglong2 X2 = P[2];
        P += 3;
        #pragma unroll
        for (int qq = 0; qq < 2; ++qq) {
            const u64 dA = fma2(q0p[qq], X0.x, fma2(q1p[qq], X1.x, fma2(q2p[qq], X2.x, nm[qq])));
            const u64 dB = fma2(q0p[qq], X0.y, fma2(q1p[qq], X1.y, fma2(q2p[qq], X2.y, nm[qq])));
            const u64 pA = ex2_2(dA);
            const u64 pB = ex2_2(dB);
            lacc[qq] = add2(lacc[qq], add2(pA, pB));
            t0[qq] = fma2(pA, X0.x, fma2(pB, X0.y, t0[qq]));
            t1[qq] = fma2(pA, X1.x, fma2(pB, X1.y, t1[qq]));
            t2[qq] = fma2(pA, X2.x, fma2(pB, X2.y, t2[qq]));
        }
    }

    // ---- Collapse packed lanes; store partials (same shift per q => plain sums) ----
    #pragma unroll
    for (int qq = 0; qq < 2; ++qq) {
        const int q = ql + qq * 32;
        float a, c;
        unpack2(lacc[qq], a, c); red[0 * 256 + g * 64 + q] = a + c;
        unpack2(t0[qq],   a, c); red[1 * 256 + g * 64 + q] = a + c;
        unpack2(t1[qq],   a, c); red[2 * 256 + g * 64 + q] = a + c;
        unpack2(t2[qq],   a, c); red[3 * 256 + g * 64 + q] = a + c;
    }
    __syncthreads();

    // ---- 4-way group merge + Wv projection + write both halves ----
    if (tid < QPC) {
        float L  = red[0 * 256 + tid] + red[0 * 256 + 64 + tid]
                 + red[0 * 256 + 128 + tid] + red[0 * 256 + 192 + tid];
        float T0 = red[1 * 256 + tid] + red[1 * 256 + 64 + tid]
                 + red[1 * 256 + 128 + tid] + red[1 * 256 + 192 + tid];
        float T1 = red[2 * 256 + tid] + red[2 * 256 + 64 + tid]
                 + red[2 * 256 + 128 + tid] + red[2 * 256 + 192 + tid];
        float T2 = red[3 * 256 + tid] + red[3 * 256 + 64 + tid]
                 + red[3 * 256 + 128 + tid] + red[3 * 256 + 192 + tid];
        const float inv = rcpa(L);
        const float* wv = Wv + h * 9;
        const float r0 = (T0 * wv[0] + T1 * wv[3] + T2 * wv[6]) * inv;
        const float r1 = (T0 * wv[1] + T1 * wv[4] + T2 * wv[7]) * inv;
        const float r2 = (T0 * wv[2] + T1 * wv[5] + T2 * wv[8]) * inv;
        const int base = (bh * S_LEN + chunk * QPC + tid) * 3;
        out[base + 0] = r0;
        out[base + 1] = r1;
        out[base + 2] = r2;
        out[OUT_HALF + base + 0] = r0;
        out[OUT_HALF + base + 1] = r1;
        out[OUT_HALF + base + 2] = r2;
    }
}

extern "C" void kernel_launch(void* const* d_in, const int* in_sizes, int n_in,
                              void* d_out, int out_size)
{
    const float* x  = (const float*)d_in[0];
    const float* Wq = (const float*)d_in[1];
    const float* Wk = (const float*)d_in[2];
    const float* Wv = (const float*)d_in[3];
    float* out = (float*)d_out;

    cudaFuncSetAttribute(attn3d_kernel,
                         cudaFuncAttributeMaxDynamicSharedMemorySize, SMEM_BYTES);
    attn3d_kernel<<<N_CTA, THREADS, SMEM_BYTES>>>(x, Wq, Wk, Wv, out);
}